// round 10
// baseline (speedup 1.0000x reference)
#include <cuda_runtime.h>
#include <cuda_fp16.h>
#include <cstdint>

#define BSZ 512
#define HD 512
#define NSTEP 256
#define NUT 32
#define NBT 8
#define NBLK 256
#define GRPC 32          // CTAs per independent bt-group
#define BM 64
#define NTH 256
// smem ring: K=128 chunk, pitch 272B per 128-half row; A 64 rows, B 64 rows
#define PITCH 272
#define OFF_B  17408
#define BUFB   34816
#define NBUF   3
#define SMEM_DYN (NBUF*BUFB)

// ---------------- persistent device state ----------------
__device__ __align__(16) __half gH0[2][BSZ][HD];
__device__ __align__(16) __half gH1[2][BSZ][HD];
__device__ __align__(16) float gC0[BSZ][HD];
__device__ __align__(16) float gC1[BSZ][HD];
__device__ float gXpart[NUT][BSZ];
__device__ unsigned gBarG[NBT];
// weights: 12 chunks x 32 u-tiles x (64 gate-rows x 128 k) fp16, k-contiguous
__device__ __align__(16) __half gWT[12][NUT][64*128];

// ---------------- helpers ----------------
__device__ __forceinline__ float sigf(float z)     { return 1.0f / (1.0f + __expf(-z)); }
__device__ __forceinline__ float tanhfast(float z) { return 2.0f / (1.0f + __expf(-2.0f * z)) - 1.0f; }

__device__ __forceinline__ uint32_t smem_u32(const void* p) {
    uint32_t a;
    asm("{ .reg .u64 t; cvta.to.shared.u64 t, %1; cvt.u32.u64 %0, t; }" : "=r"(a) : "l"(p));
    return a;
}
__device__ __forceinline__ void cpa16(uint32_t d, const void* s) {
    asm volatile("cp.async.cg.shared.global [%0], [%1], 16;"
                 :: "r"(d), "l"(__cvta_generic_to_global(s)) : "memory");
}
#define CP_COMMIT() asm volatile("cp.async.commit_group;" ::: "memory")

#define LDX4(r, a) \
    asm volatile("ldmatrix.sync.aligned.m8n8.x4.shared.b16 {%0,%1,%2,%3}, [%4];" \
        : "=r"((r)[0]), "=r"((r)[1]), "=r"((r)[2]), "=r"((r)[3]) : "r"(a))

#define MMA(d, a, b) \
    asm volatile("mma.sync.aligned.m16n8k16.row.col.f32.f16.f16.f32 " \
        "{%0,%1,%2,%3}, {%4,%5,%6,%7}, {%8,%9}, {%0,%1,%2,%3};" \
        : "+f"((d)[0]), "+f"((d)[1]), "+f"((d)[2]), "+f"((d)[3]) \
        : "r"((a)[0]), "r"((a)[1]), "r"((a)[2]), "r"((a)[3]), "r"((b)[0]), "r"((b)[1]))

// ---------------- init: states + fp16 weight transform ----------------
__global__ void init_kernel(const float* __restrict__ h, const float* __restrict__ c,
                            const float* __restrict__ W_hh0, const float* __restrict__ W_ih1,
                            const float* __restrict__ W_hh1)
{
    const int gtid = blockIdx.x * blockDim.x + threadIdx.x;
    const int gsz  = gridDim.x * blockDim.x;
    if (gtid < NBT) gBarG[gtid] = 0u;

    const int n = BSZ * HD;
    for (int i = gtid; i < n; i += gsz) {
        (&gH0[0][0][0])[i] = __float2half(h[i]);
        (&gH1[0][0][0])[i] = __float2half(h[n + i]);
        (&gC0[0][0])[i] = c[i];
        (&gC1[0][0])[i] = c[n + i];
    }

    const long WN = 12L * NUT * 64 * 128;
    for (long idx = gtid; idx < WN; idx += gsz) {
        const int kk   = (int)(idx & 127);
        const int nrow = (int)((idx >> 7) & 63);
        const int ut   = (int)((idx >> 13) & 31);
        const int ch   = (int)(idx >> 18);
        const float* W = (ch < 4) ? W_hh0 : ((ch < 8) ? W_ih1 : W_hh1);
        // gate-row r -> weight row j: gate = r&3, unit = r>>2
        const int j = (nrow & 3) * HD + ut * 16 + (nrow >> 2);
        gWT[ch][ut][nrow * 128 + kk] = __float2half(W[(size_t)j * HD + (ch & 3) * 128 + kk]);
    }
}

// ---------------- main persistent kernel ----------------
__global__ void __launch_bounds__(NTH, 2) lstm_tc_kernel(
    const float* __restrict__ W_ih0,
    const float* __restrict__ b_ih0, const float* __restrict__ b_hh0,
    const float* __restrict__ b_ih1, const float* __restrict__ b_hh1,
    const float* __restrict__ fc_w,  const float* __restrict__ fc_b,
    float* __restrict__ out)
{
    extern __shared__ unsigned char sbuf[];

    __shared__ float sx[BM];
    __shared__ float sp[4][BM];
    __shared__ float sbias0[64], swih0[64], sbias1[64], sfcw16[16];

    const int tid = threadIdx.x;
    const int lid = tid & 31;
    const int wid = tid >> 5;
    const int wm  = wid & 1;          // M tile: rows wm*32..+31
    const int wn  = wid >> 1;         // N tile: gate-rows wn*16..+15 (units wn*4..+3)
    const int bt  = blockIdx.x >> 5;
    const int ut  = blockIdx.x & 31;
    const int b0  = bt * BM;
    const int u0  = ut * 16;
    const float fcb = fc_b[0];
    const uint32_t sb32 = smem_u32(sbuf);

    if (tid < 64) {
        const int lu = tid >> 2, g = tid & 3;
        const int j = g * HD + u0 + lu;
        sbias0[tid] = b_ih0[j] + b_hh0[j];
        swih0[tid]  = W_ih0[j];
        sbias1[tid] = b_ih1[j] + b_hh1[j];
    }
    if (tid < 16) sfcw16[tid] = fc_w[u0 + tid];
    __syncthreads();

    float acc[2][2][4];
    unsigned nbar = 0;

    // ---- group barrier over the 32 CTAs of this bt-group
    auto grid_sync = [&]() {
        __threadfence();
        __syncthreads();
        nbar++;
        if (tid == 0) {
            atomicAdd(&gBarG[bt], 1u);
            const unsigned target = nbar * GRPC;
            while (*((volatile unsigned*)&gBarG[bt]) < target) __nanosleep(64);
        }
        __syncthreads();
    };

    // ---- stage chunk c into ring buffer r (A: fp16 h rows b0..b0+63; B: weights)
    auto stage = [&](int c, int r, int rp, int wp) {
        const __half* Ah; int k0;
        if (c < 4)      { Ah = &gH0[rp][0][0]; k0 = c * 128; }
        else if (c < 8) { Ah = &gH0[wp][0][0]; k0 = (c - 4) * 128; }
        else            { Ah = &gH1[rp][0][0]; k0 = (c - 8) * 128; }
        const uint32_t bb = sb32 + r * BUFB;
        #pragma unroll
        for (int i = 0; i < 4; ++i) {   // A: 1024 segs (64 rows x 16)
            const int s = tid + i * NTH;
            const int row = s >> 4, seg = s & 15;
            cpa16(bb + row * PITCH + seg * 16,
                  Ah + (size_t)(b0 + row) * HD + k0 + seg * 8);
        }
        #pragma unroll
        for (int i = 0; i < 4; ++i) {   // B: 1024 segs (64 rows x 16)
            const int s = tid + i * NTH;
            const int row = s >> 4, seg = s & 15;
            cpa16(bb + OFF_B + row * PITCH + seg * 16,
                  &gWT[c][ut][row * 128 + seg * 8]);
        }
        CP_COMMIT();
    };

    // ---- compute one K=128 chunk from ring buffer r into acc
    auto compute = [&](int r) {
        const uint32_t bb = sb32 + r * BUFB;
        const uint32_t aoff = (wm * 32 + (lid & 15)) * PITCH + (lid >> 4) * 16;
        const uint32_t boff = OFF_B + (wn * 16 + (lid & 15)) * PITCH + (lid >> 4) * 16;
        #pragma unroll
        for (int ks = 0; ks < 8; ++ks) {
            const uint32_t ko = ks * 32;
            uint32_t Af[2][4];
            LDX4(Af[0], bb + aoff + ko);
            LDX4(Af[1], bb + aoff + 16 * PITCH + ko);
            uint32_t t0[4];
            LDX4(t0, bb + boff + ko);
            uint32_t Bf[2][2];
            Bf[0][0] = t0[0]; Bf[0][1] = t0[2];
            Bf[1][0] = t0[1]; Bf[1][1] = t0[3];
            #pragma unroll
            for (int mt = 0; mt < 2; ++mt)
                #pragma unroll
                for (int nt = 0; nt < 2; ++nt)
                    MMA(acc[mt][nt], Af[mt], Bf[nt]);
        }
    };

    // ---- run chunks [ca,cb]: 3-deep ring, stage 1 ahead, 1 sync/chunk
    auto run_layer = [&](int ca, int cb, int rp, int wp) {
        #pragma unroll
        for (int mt = 0; mt < 2; ++mt)
            #pragma unroll
            for (int nt = 0; nt < 2; ++nt)
                #pragma unroll
                for (int q = 0; q < 4; ++q) acc[mt][nt][q] = 0.0f;
        stage(ca, 0, rp, wp);
        int r = 0;
        #pragma unroll 1
        for (int c = ca; c <= cb; ++c) {
            if (c + 1 <= cb) {
                int rn = r + 1; if (rn == NBUF) rn = 0;
                stage(c + 1, rn, rp, wp);
                asm volatile("cp.async.wait_group 1;" ::: "memory");
            } else {
                asm volatile("cp.async.wait_group 0;" ::: "memory");
            }
            __syncthreads();
            compute(r);
            if (++r == NBUF) r = 0;
        }
    };

    // ---- fused LSTM epilogue from register accumulators
    const int mbase = wm * 32 + (lid >> 2) + ((lid & 1) ? 8 : 0);
    const int lusub = wn * 4 + ((lid & 3) >> 1);

    auto epilogue = [&](bool L1, const float* sbias, float* Cbase, __half* Hb) {
        #pragma unroll
        for (int mt = 0; mt < 2; ++mt) {
            const int bl = mbase + mt * 16;
            const float xb = L1 ? 0.0f : sx[bl];
            float pb = 0.0f;
            #pragma unroll
            for (int nt = 0; nt < 2; ++nt) {
                float* d = acc[mt][nt];
                const float e0 = __shfl_xor_sync(0xFFFFFFFFu, d[0], 1);
                const float e1 = __shfl_xor_sync(0xFFFFFFFFu, d[1], 1);
                const float e2 = __shfl_xor_sync(0xFFFFFFFFu, d[2], 1);
                const float e3 = __shfl_xor_sync(0xFFFFFFFFu, d[3], 1);
                float gi, gf, gg, go;
                if (!(lid & 1)) { gi = d[0]; gf = d[1]; gg = e0; go = e1; }
                else            { gi = e2;  gf = e3;  gg = d[2]; go = d[3]; }
                const int lun = lusub + nt * 2;
                gi += sbias[4*lun+0]; gf += sbias[4*lun+1];
                gg += sbias[4*lun+2]; go += sbias[4*lun+3];
                if (!L1) {
                    gi += xb * swih0[4*lun+0]; gf += xb * swih0[4*lun+1];
                    gg += xb * swih0[4*lun+2]; go += xb * swih0[4*lun+3];
                }
                const size_t off = (size_t)(b0 + bl) * HD + u0 + lun;
                const float cold = Cbase[off];
                const float cn = sigf(gf) * cold + sigf(gi) * tanhfast(gg);
                const float hn = sigf(go) * tanhfast(cn);
                Cbase[off] = cn;
                Hb[off] = __float2half(hn);
                if (L1) pb += hn * sfcw16[lun];
            }
            if (L1) {
                pb += __shfl_xor_sync(0xFFFFFFFFu, pb, 2);
                if (!(lid & 2)) sp[wn][bl] = pb;
            }
        }
    };

    #pragma unroll 1
    for (int t = 0; t < NSTEP; ++t) {
        const int rp = t & 1, wp = rp ^ 1;

        // ---- x_t from distributed fc partials
        if (t == 0) {
            if (tid < BM) sx[tid] = 0.0f;
        } else if (tid < BM) {
            float x = fcb;
            #pragma unroll
            for (int j = 0; j < NUT; ++j) x += __ldcg(&gXpart[j][b0 + tid]);
            sx[tid] = x;
            if (ut == 0) out[(size_t)(b0 + tid) * NSTEP + (t - 1)] = x;
        }

        // ---- layer 0: K=512 (chunks 0..3), fused update
        run_layer(0, 3, rp, wp);
        epilogue(false, sbias0, &gC0[0][0], &gH0[wp][0][0]);
        grid_sync();

        // ---- layer 1: K=1024 (chunks 4..11), fused update + fc partial
        run_layer(4, 11, rp, wp);
        epilogue(true, sbias1, &gC1[0][0], &gH1[wp][0][0]);
        __syncthreads();
        if (tid < BM) gXpart[ut][b0 + tid] = sp[0][tid] + sp[1][tid] + sp[2][tid] + sp[3][tid];
        grid_sync();
    }

    // ---- final prediction column 255
    if (ut == 0 && tid < BM) {
        float x = fcb;
        #pragma unroll
        for (int j = 0; j < NUT; ++j) x += __ldcg(&gXpart[j][b0 + tid]);
        out[(size_t)(b0 + tid) * NSTEP + 255] = x;
    }
}

extern "C" void kernel_launch(void* const* d_in, const int* in_sizes, int n_in,
                              void* d_out, int out_size)
{
    const float* h     = (const float*)d_in[0];
    const float* c     = (const float*)d_in[1];
    const float* W_ih0 = (const float*)d_in[2];
    const float* W_hh0 = (const float*)d_in[3];
    const float* b_ih0 = (const float*)d_in[4];
    const float* b_hh0 = (const float*)d_in[5];
    const float* W_ih1 = (const float*)d_in[6];
    const float* W_hh1 = (const float*)d_in[7];
    const float* b_ih1 = (const float*)d_in[8];
    const float* b_hh1 = (const float*)d_in[9];
    const float* fc_w  = (const float*)d_in[10];
    const float* fc_b  = (const float*)d_in[11];

    cudaFuncSetAttribute(lstm_tc_kernel, cudaFuncAttributeMaxDynamicSharedMemorySize, SMEM_DYN);

    init_kernel<<<1024, 256>>>(h, c, W_hh0, W_ih1, W_hh1);
    lstm_tc_kernel<<<NBLK, NTH, SMEM_DYN>>>(W_ih0, b_ih0, b_hh0, b_ih1, b_hh1,
                                            fc_w, fc_b, (float*)d_out);
}